// round 2
// baseline (speedup 1.0000x reference)
#include <cuda_runtime.h>

// ---------------- constants ----------------
#define C_NUM   80
#define TOPK_N  1000
#define CONF_T  0.05f
#define NMS_THR 0.6f
#define IMG_INV (1.0f/2048.0f)
#define HBINS   16384
#define CAND_CAP 32768
#define SH_CAP  16384
#define N_ALL   3000

// ---------------- device scratch (no allocations allowed) ----------------
__device__ float              g_b[196608];
__device__ unsigned int       g_hist[HBINS];
__device__ unsigned int       g_cnt;
__device__ unsigned int       g_Tbits;
__device__ unsigned long long g_cand[CAND_CAP];
__device__ unsigned long long g_topk[3][TOPK_N];
__device__ float   g_score[N_ALL];
__device__ int     g_label[N_ALL];
__device__ float4  g_box[N_ALL];
__device__ float   g_sscore[N_ALL];
__device__ int     g_slabel[N_ALL];
__device__ float4  g_sbox[N_ALL];
__device__ int     g_keep[N_ALL];

__device__ __forceinline__ float sigm(float x) { return 1.0f / (1.0f + expf(-x)); }

// ---------------- kernels ----------------
__global__ void zero_hist_kernel() {
    int i = blockIdx.x * blockDim.x + threadIdx.x;
    if (i < HBINS) g_hist[i] = 0u;
}

// 4 threads per anchor row (80 cls values = 20 float4). Computes
// b_m = sqrt(sig(obj)*sig(max_c cls)), stores it, histograms its float bits >> 16.
__global__ void rowmax_kernel(const float* __restrict__ obj,
                              const float* __restrict__ cls, int M) {
    int g = blockIdx.x * blockDim.x + threadIdx.x;
    int row = g >> 2;
    int sub = g & 3;
    if (row >= M) return;
    const float4* c4 = reinterpret_cast<const float4*>(cls) + (size_t)row * 20;
    float mx = -1e30f;
#pragma unroll
    for (int it = 0; it < 5; it++) {
        float4 v = c4[it * 4 + sub];
        mx = fmaxf(mx, fmaxf(fmaxf(v.x, v.y), fmaxf(v.z, v.w)));
    }
    mx = fmaxf(mx, __shfl_xor_sync(0xFFFFFFFFu, mx, 1));
    mx = fmaxf(mx, __shfl_xor_sync(0xFFFFFFFFu, mx, 2));
    if (sub == 0) {
        float so = sigm(obj[row]);
        float sc = sigm(mx);
        float b = sqrtf(so * sc);
        g_b[row] = b;
        atomicAdd(&g_hist[__float_as_uint(b) >> 16], 1u);
    }
}

// Single block: find threshold bucket so that count(b >= T) >= 1000.
__global__ void findT_kernel() {
    __shared__ unsigned int csum[256];
    unsigned int s = 0;
    int base = threadIdx.x * 64;
    for (int i = 0; i < 64; i++) s += g_hist[base + i];
    csum[threadIdx.x] = s;
    __syncthreads();
    if (threadIdx.x == 0) {
        unsigned int cum = 0;
        int ch = 255;
        for (; ch > 0; ch--) {
            if (cum + csum[ch] >= TOPK_N) break;
            cum += csum[ch];
        }
        int bin = ch * 64 + 63;
        for (; bin > ch * 64; bin--) {
            cum += g_hist[bin];
            if (cum >= TOPK_N) break;
        }
        if (cum < TOPK_N) cum += g_hist[ch * 64]; // bin == ch*64 fallthrough
        g_Tbits = ((unsigned int)bin) << 16;
        g_cnt = 0;
    }
}

// Sparse pass: only anchor rows with b_m (+slack) >= T are expanded.
// Appends candidates (scorebits, idx) with scorebits >= T.
__global__ void compact_kernel(const float* __restrict__ obj,
                               const float* __restrict__ cls, int M) {
    int g = blockIdx.x * blockDim.x + threadIdx.x;
    int row = g >> 2;
    int sub = g & 3;
    if (row >= M) return;
    unsigned int T = g_Tbits;
    unsigned int bb = __float_as_uint(g_b[row]);
    if (bb + 64u < T) return;  // slack covers expf non-monotonicity ulps
    float so = sigm(obj[row]);
    const float4* c4 = reinterpret_cast<const float4*>(cls) + (size_t)row * 20;
#pragma unroll
    for (int it = 0; it < 5; it++) {
        float4 v = c4[it * 4 + sub];
        float vv[4] = {v.x, v.y, v.z, v.w};
#pragma unroll
        for (int k = 0; k < 4; k++) {
            float s = sqrtf(so * sigm(vv[k]));
            unsigned int sb = __float_as_uint(s);
            if (sb >= T) {
                unsigned int p = atomicAdd(&g_cnt, 1u);
                if (p < CAND_CAP) {
                    int idx = row * C_NUM + (it * 4 + sub) * 4 + k;
                    g_cand[p] = ((unsigned long long)sb << 24) |
                                (unsigned long long)(0xFFFFFF - idx);
                }
            }
        }
    }
}

// Descending bitonic sort (ties resolved by key low bits). Block-wide.
__device__ void bitonic_desc(unsigned long long* s, int n) {
    for (int k = 2; k <= n; k <<= 1) {
        for (int j = k >> 1; j > 0; j >>= 1) {
            for (int t = threadIdx.x; t < n; t += blockDim.x) {
                int l = t ^ j;
                if (l > t) {
                    unsigned long long a = s[t], b = s[l];
                    bool dir = ((t & k) == 0);  // descending region
                    if (dir ? (a < b) : (a > b)) { s[t] = b; s[l] = a; }
                }
            }
            __syncthreads();
        }
    }
}

__global__ void sort_topk_kernel(int lvl) {
    extern __shared__ unsigned long long sh[];
    unsigned int cnt = g_cnt;
    if (cnt > CAND_CAP) cnt = CAND_CAP;
    int n = 1024;
    while (n < (int)cnt) n <<= 1;
    if (n <= SH_CAP) {
        for (int i = threadIdx.x; i < n; i += blockDim.x)
            sh[i] = (i < (int)cnt) ? g_cand[i] : 0ULL;
        __syncthreads();
        bitonic_desc(sh, n);
        for (int i = threadIdx.x; i < TOPK_N; i += blockDim.x)
            g_topk[lvl][i] = sh[i];
    } else {
        for (int i = (int)cnt + (int)threadIdx.x; i < n; i += blockDim.x)
            g_cand[i] = 0ULL;
        __syncthreads();
        bitonic_desc(g_cand, n);
        for (int i = threadIdx.x; i < TOPK_N; i += blockDim.x)
            g_topk[lvl][i] = g_cand[i];
    }
}

__global__ void decode_kernel(const float* __restrict__ r0,
                              const float* __restrict__ r1,
                              const float* __restrict__ r2,
                              const float* __restrict__ anc) {
    int i = blockIdx.x * blockDim.x + threadIdx.x;
    if (i >= N_ALL) return;
    int lvl = i / TOPK_N;
    unsigned long long key = g_topk[lvl][i - lvl * TOPK_N];
    unsigned int sb = (unsigned int)(key >> 24);
    int idx = 0xFFFFFF - (int)(key & 0xFFFFFFULL);
    int c = idx % C_NUM;
    int m = idx / C_NUM;
    int a = m % 3;
    int cell = m / 3;
    int W = (lvl == 0) ? 256 : ((lvl == 1) ? 128 : 64);
    float stride = (lvl == 0) ? 8.0f : ((lvl == 1) ? 16.0f : 32.0f);
    int x = cell % W, y = cell / W;
    const float* reg = ((lvl == 0) ? r0 : ((lvl == 1) ? r1 : r2)) + (size_t)m * 4;
    float cx = ((float)x + 0.5f) * stride + (sigm(reg[0]) * 3.0f - 1.5f) * stride;
    float cy = ((float)y + 0.5f) * stride + (sigm(reg[1]) * 3.0f - 1.5f) * stride;
    float bw = expf(reg[2]) * anc[lvl * 6 + a * 2 + 0];
    float bh = expf(reg[3]) * anc[lvl * 6 + a * 2 + 1];
    float4 b;
    b.x = cx - 0.5f * bw;
    b.y = cy - 0.5f * bh;
    b.z = cx + 0.5f * bw;
    b.w = cy + 0.5f * bh;
    g_box[i] = b;
    float s = __uint_as_float(sb);
    g_score[i] = (s > CONF_T) ? s : 0.0f;
    g_label[i] = c;
}

// Global stable sort of 3000 entries by score desc (ties: earlier position first).
__global__ void gsort_kernel() {
    __shared__ unsigned long long sh[4096];
    for (int i = threadIdx.x; i < 4096; i += blockDim.x) {
        if (i < N_ALL) {
            unsigned int sb = __float_as_uint(g_score[i]);
            sh[i] = ((unsigned long long)sb << 12) | (unsigned long long)(4095 - i);
        } else {
            sh[i] = 0ULL;
        }
    }
    __syncthreads();
    bitonic_desc(sh, 4096);
    for (int i = threadIdx.x; i < N_ALL; i += blockDim.x) {
        int p = 4095 - (int)(sh[i] & 0xFFFULL);
        g_sscore[i] = g_score[p];
        g_slabel[i] = g_label[p];
        g_sbox[i]   = g_box[p];
        g_keep[i]   = 0;
    }
}

// Per-class greedy NMS (class offset makes cross-class IoU == 0).
// Uses OFFSET-quantized boxes exactly like the reference (f32 + label*1e5).
__global__ void nms_kernel() {
    int c = blockIdx.x;  // 80 blocks
    __shared__ int s_n;
    __shared__ int s_wsum[4];
    __shared__ int s_pos[1024];
    __shared__ float4 s_box[1024];
    __shared__ float s_area[1024];
    __shared__ unsigned char s_supp[1024];
    if (threadIdx.x == 0) s_n = 0;
    __syncthreads();
    int lane = threadIdx.x & 31;
    int w = threadIdx.x >> 5;
    float offv = (float)c * 100000.0f;
    for (int base = 0; base < N_ALL; base += 128) {
        int i = base + threadIdx.x;
        bool pred = (i < N_ALL) && (g_slabel[i] == c) && (g_sscore[i] > CONF_T);
        unsigned int bal = __ballot_sync(0xFFFFFFFFu, pred);
        if (lane == 0) s_wsum[w] = __popc(bal);
        __syncthreads();
        int off = s_n;
        for (int ww = 0; ww < w; ww++) off += s_wsum[ww];
        int rank = off + __popc(bal & ((1u << lane) - 1u));
        if (pred && rank < 1024) {
            s_pos[rank] = i;
            float4 b = g_sbox[i];
            b.x += offv; b.y += offv; b.z += offv; b.w += offv;  // reproduce quantization
            s_box[rank] = b;
            s_area[rank] = (b.z - b.x) * (b.w - b.y);
            s_supp[rank] = 0;
        }
        __syncthreads();
        if (threadIdx.x == 0) s_n += s_wsum[0] + s_wsum[1] + s_wsum[2] + s_wsum[3];
        __syncthreads();
    }
    int n = (s_n < 1024) ? s_n : 1024;
    for (int a = 0; a < n; a++) {
        if (!s_supp[a]) {
            if (threadIdx.x == 0) g_keep[s_pos[a]] = 1;
            float4 A = s_box[a];
            float arA = s_area[a];
            for (int b = a + 1 + (int)threadIdx.x; b < n; b += 128) {
                if (s_supp[b]) continue;
                float4 B = s_box[b];
                float ltx = fmaxf(A.x, B.x), lty = fmaxf(A.y, B.y);
                float rbx = fminf(A.z, B.z), rby = fminf(A.w, B.w);
                float wx = fmaxf(rbx - ltx, 0.0f), wy = fmaxf(rby - lty, 0.0f);
                float inter = wx * wy;
                float iou = inter / (arA + s_area[b] - inter + 1e-12f);
                if (iou > NMS_THR) s_supp[b] = 1;
            }
        }
        __syncthreads();
    }
}

__global__ void output_kernel(float* __restrict__ out) {
    int i = blockIdx.x * blockDim.x + threadIdx.x;
    if (i >= N_ALL) return;
    float4 b = g_sbox[i];
    out[i * 4 + 0] = fminf(fmaxf(b.x * IMG_INV, 0.0f), 1.0f);
    out[i * 4 + 1] = fminf(fmaxf(b.y * IMG_INV, 0.0f), 1.0f);
    out[i * 4 + 2] = fminf(fmaxf(b.z * IMG_INV, 0.0f), 1.0f);
    out[i * 4 + 3] = fminf(fmaxf(b.w * IMG_INV, 0.0f), 1.0f);
    out[12000 + i] = g_keep[i] ? g_sscore[i] : 0.0f;
    out[15000 + i] = (float)g_slabel[i];
}

// ---------------- launcher ----------------
extern "C" void kernel_launch(void* const* d_in, const int* in_sizes, int n_in,
                              void* d_out, int out_size) {
    (void)in_sizes; (void)n_in; (void)out_size;
    const float* obj[3] = {(const float*)d_in[0], (const float*)d_in[3], (const float*)d_in[6]};
    const float* cls[3] = {(const float*)d_in[1], (const float*)d_in[4], (const float*)d_in[7]};
    const float* reg[3] = {(const float*)d_in[2], (const float*)d_in[5], (const float*)d_in[8]};
    const float* anc    = (const float*)d_in[9];
    const int M[3] = {196608, 49152, 12288};

    cudaFuncSetAttribute(sort_topk_kernel,
                         cudaFuncAttributeMaxDynamicSharedMemorySize, SH_CAP * 8);

    for (int l = 0; l < 3; l++) {
        zero_hist_kernel<<<16, 1024>>>();
        rowmax_kernel<<<M[l] / 64, 256>>>(obj[l], cls[l], M[l]);
        findT_kernel<<<1, 256>>>();
        compact_kernel<<<M[l] / 64, 256>>>(obj[l], cls[l], M[l]);
        sort_topk_kernel<<<1, 1024, SH_CAP * 8>>>(l);
    }
    decode_kernel<<<12, 256>>>(reg[0], reg[1], reg[2], anc);
    gsort_kernel<<<1, 1024>>>();
    nms_kernel<<<80, 128>>>();
    output_kernel<<<12, 256>>>((float*)d_out);
}

// round 3
// speedup vs baseline: 1.5331x; 1.5331x over previous
#include <cuda_runtime.h>

// ---------------- constants ----------------
#define C_NUM   80
#define TOPK_N  1000
#define CONF_T  0.05f
#define NMS_THR 0.6f
#define IMG_INV (1.0f/2048.0f)
#define HBINS   16384
#define CAND_CAP 32768
#define SH_CAP  16384
#define N_ALL   3000
#define ROWS0   196608
#define ROWS1   49152
#define ROWS2   12288
#define RTOT    258048   // ROWS0+ROWS1+ROWS2

// ---------------- device scratch ----------------
__device__ float              g_b[RTOT];
__device__ unsigned int       g_hist[3 * HBINS];
__device__ unsigned int       g_cnt[3];
__device__ unsigned int       g_Tbits[3];
__device__ unsigned long long g_cand[3][CAND_CAP];
__device__ unsigned long long g_topk[3][TOPK_N];
__device__ float4  g_box[N_ALL];
__device__ float   g_sscore[N_ALL];
__device__ int     g_slabel[N_ALL];
__device__ float4  g_sbox[N_ALL];

__device__ __forceinline__ float sigm(float x) { return 1.0f / (1.0f + expf(-x)); }

// Map a global row index to (level, local row). Blocks are level-aligned:
// ROWS0*4/256 = 3072 blocks, ROWS1*4/256 = 768, ROWS2*4/256 = 192.
__device__ __forceinline__ void level_of(int grow, int& lvl, int& r) {
    if (grow < ROWS0)            { lvl = 0; r = grow; }
    else if (grow < ROWS0+ROWS1) { lvl = 1; r = grow - ROWS0; }
    else                         { lvl = 2; r = grow - ROWS0 - ROWS1; }
}

// ---------------- kernels ----------------
__global__ void zero_kernel() {
    int i = blockIdx.x * blockDim.x + threadIdx.x;
    if (i < 3 * HBINS) g_hist[i] = 0u;
}

// All 3 levels fused. 4 threads per anchor row.
__global__ void rowmax_all(const float* __restrict__ obj0, const float* __restrict__ cls0,
                           const float* __restrict__ obj1, const float* __restrict__ cls1,
                           const float* __restrict__ obj2, const float* __restrict__ cls2) {
    int g = blockIdx.x * blockDim.x + threadIdx.x;
    int grow = g >> 2;
    int sub = g & 3;
    if (grow >= RTOT) return;
    int lvl, r;
    level_of(grow, lvl, r);
    const float* obj = (lvl == 0) ? obj0 : ((lvl == 1) ? obj1 : obj2);
    const float* cls = (lvl == 0) ? cls0 : ((lvl == 1) ? cls1 : cls2);

    const float4* c4 = reinterpret_cast<const float4*>(cls) + (size_t)r * 20;
    float mx = -1e30f;
#pragma unroll
    for (int it = 0; it < 5; it++) {
        float4 v = c4[it * 4 + sub];
        mx = fmaxf(mx, fmaxf(fmaxf(v.x, v.y), fmaxf(v.z, v.w)));
    }
    mx = fmaxf(mx, __shfl_xor_sync(0xFFFFFFFFu, mx, 1));
    mx = fmaxf(mx, __shfl_xor_sync(0xFFFFFFFFu, mx, 2));
    if (sub == 0) {
        float so = sigm(obj[r]);
        float b = sqrtf(so * sigm(mx));
        g_b[grow] = b;
        atomicAdd(&g_hist[lvl * HBINS + (__float_as_uint(b) >> 16)], 1u);
    }
}

// 3 blocks, one per level. Two-level scan, no serial global-latency chains.
__global__ void findT_all() {
    int lvl = blockIdx.x;
    __shared__ unsigned int csum[256];
    __shared__ unsigned int cbins[64];
    __shared__ int s_ch;
    __shared__ unsigned int s_cum;
    unsigned int s = 0;
    int base = lvl * HBINS + threadIdx.x * 64;
#pragma unroll 8
    for (int i = 0; i < 64; i++) s += g_hist[base + i];
    csum[threadIdx.x] = s;
    __syncthreads();
    if (threadIdx.x == 0) {
        unsigned int cum = 0;
        int ch = 255;
        for (; ch > 0; ch--) {
            if (cum + csum[ch] >= TOPK_N) break;
            cum += csum[ch];
        }
        s_ch = ch;
        s_cum = cum;
    }
    __syncthreads();
    int ch = s_ch;
    if (threadIdx.x < 64)
        cbins[threadIdx.x] = g_hist[lvl * HBINS + ch * 64 + threadIdx.x];
    __syncthreads();
    if (threadIdx.x == 0) {
        unsigned int cum = s_cum;
        int bin = 63;
        for (; bin > 0; bin--) {
            cum += cbins[bin];
            if (cum >= TOPK_N) break;
        }
        // if loop exhausted, bin==0 (chunk selection guarantees bin0 completes it)
        g_Tbits[lvl] = ((unsigned int)(ch * 64 + bin)) << 16;
        g_cnt[lvl] = 0u;
    }
}

// Sparse second pass, all levels fused. T broadcast via shared (the per-thread
// single-address LDG of g_Tbits was the round-2 latency killer).
__global__ void compact_all(const float* __restrict__ obj0, const float* __restrict__ cls0,
                            const float* __restrict__ obj1, const float* __restrict__ cls1,
                            const float* __restrict__ obj2, const float* __restrict__ cls2) {
    __shared__ unsigned int sT[3];
    if (threadIdx.x < 3) sT[threadIdx.x] = g_Tbits[threadIdx.x];
    __syncthreads();
    int g = blockIdx.x * blockDim.x + threadIdx.x;
    int grow = g >> 2;
    int sub = g & 3;
    if (grow >= RTOT) return;
    int lvl, r;
    level_of(grow, lvl, r);
    unsigned int T = sT[lvl];
    unsigned int bb = __float_as_uint(g_b[grow]);
    if (bb + 64u < T) return;  // ulp slack for expf path differences
    const float* obj = (lvl == 0) ? obj0 : ((lvl == 1) ? obj1 : obj2);
    const float* cls = (lvl == 0) ? cls0 : ((lvl == 1) ? cls1 : cls2);
    float so = sigm(obj[r]);
    const float4* c4 = reinterpret_cast<const float4*>(cls) + (size_t)r * 20;
#pragma unroll
    for (int it = 0; it < 5; it++) {
        float4 v = c4[it * 4 + sub];
        float vv[4] = {v.x, v.y, v.z, v.w};
#pragma unroll
        for (int k = 0; k < 4; k++) {
            float sc = sqrtf(so * sigm(vv[k]));
            unsigned int sb = __float_as_uint(sc);
            if (sb >= T) {
                unsigned int p = atomicAdd(&g_cnt[lvl], 1u);
                if (p < CAND_CAP) {
                    int idx = r * C_NUM + (it * 4 + sub) * 4 + k;
                    g_cand[lvl][p] = ((unsigned long long)sb << 24) |
                                     (unsigned long long)(0xFFFFFF - idx);
                }
            }
        }
    }
}

__device__ void bitonic_desc(unsigned long long* s, int n) {
    for (int k = 2; k <= n; k <<= 1) {
        for (int j = k >> 1; j > 0; j >>= 1) {
            for (int t = threadIdx.x; t < n; t += blockDim.x) {
                int l = t ^ j;
                if (l > t) {
                    unsigned long long a = s[t], b = s[l];
                    bool dir = ((t & k) == 0);
                    if (dir ? (a < b) : (a > b)) { s[t] = b; s[l] = a; }
                }
            }
            __syncthreads();
        }
    }
}

// 3 concurrent blocks, one per level.
__global__ void sort_topk_all() {
    extern __shared__ unsigned long long sh[];
    int lvl = blockIdx.x;
    unsigned int cnt = g_cnt[lvl];
    if (cnt > CAND_CAP) cnt = CAND_CAP;
    int n = 1024;
    while (n < (int)cnt) n <<= 1;
    if (n <= SH_CAP) {
        for (int i = threadIdx.x; i < n; i += blockDim.x)
            sh[i] = (i < (int)cnt) ? g_cand[lvl][i] : 0ULL;
        __syncthreads();
        bitonic_desc(sh, n);
        for (int i = threadIdx.x; i < TOPK_N; i += blockDim.x)
            g_topk[lvl][i] = sh[i];
    } else {
        for (int i = (int)cnt + (int)threadIdx.x; i < n; i += blockDim.x)
            g_cand[lvl][i] = 0ULL;
        __syncthreads();
        bitonic_desc(g_cand[lvl], n);
        for (int i = threadIdx.x; i < TOPK_N; i += blockDim.x)
            g_topk[lvl][i] = g_cand[lvl][i];
    }
}

// Fused: decode all 3000 + global stable sort + write boxes/labels/zero-scores.
__global__ void fuse_kernel(const float* __restrict__ r0,
                            const float* __restrict__ r1,
                            const float* __restrict__ r2,
                            const float* __restrict__ anc,
                            float* __restrict__ out) {
    __shared__ unsigned long long sh[4096];
    __shared__ int slab[N_ALL];
    for (int i = threadIdx.x; i < 4096; i += blockDim.x) {
        if (i < N_ALL) {
            int lvl = i / TOPK_N;
            unsigned long long key = g_topk[lvl][i - lvl * TOPK_N];
            unsigned int sb = (unsigned int)(key >> 24);
            int idx = 0xFFFFFF - (int)(key & 0xFFFFFFULL);
            int c = idx % C_NUM;
            int m = idx / C_NUM;
            int a = m % 3;
            int cell = m / 3;
            int W = (lvl == 0) ? 256 : ((lvl == 1) ? 128 : 64);
            float stride = (lvl == 0) ? 8.0f : ((lvl == 1) ? 16.0f : 32.0f);
            int x = cell % W, y = cell / W;
            const float* reg = ((lvl == 0) ? r0 : ((lvl == 1) ? r1 : r2)) + (size_t)m * 4;
            float cx = ((float)x + 0.5f) * stride + (sigm(reg[0]) * 3.0f - 1.5f) * stride;
            float cy = ((float)y + 0.5f) * stride + (sigm(reg[1]) * 3.0f - 1.5f) * stride;
            float bw = expf(reg[2]) * anc[lvl * 6 + a * 2 + 0];
            float bh = expf(reg[3]) * anc[lvl * 6 + a * 2 + 1];
            float4 b;
            b.x = cx - 0.5f * bw; b.y = cy - 0.5f * bh;
            b.z = cx + 0.5f * bw; b.w = cy + 0.5f * bh;
            g_box[i] = b;
            float s = __uint_as_float(sb);
            s = (s > CONF_T) ? s : 0.0f;
            slab[i] = c;
            sh[i] = ((unsigned long long)__float_as_uint(s) << 12) |
                    (unsigned long long)(4095 - i);
        } else {
            sh[i] = 0ULL;
        }
    }
    __syncthreads();
    bitonic_desc(sh, 4096);
    for (int i = threadIdx.x; i < N_ALL; i += blockDim.x) {
        unsigned long long k = sh[i];
        int p = 4095 - (int)(k & 0xFFFULL);
        float s = __uint_as_float((unsigned int)(k >> 12));
        float4 b = g_box[p];
        g_sbox[i] = b;
        g_sscore[i] = s;
        g_slabel[i] = slab[p];
        out[i * 4 + 0] = fminf(fmaxf(b.x * IMG_INV, 0.0f), 1.0f);
        out[i * 4 + 1] = fminf(fmaxf(b.y * IMG_INV, 0.0f), 1.0f);
        out[i * 4 + 2] = fminf(fmaxf(b.z * IMG_INV, 0.0f), 1.0f);
        out[i * 4 + 3] = fminf(fmaxf(b.w * IMG_INV, 0.0f), 1.0f);
        out[12000 + i] = 0.0f;           // suppressed/low-conf default; NMS fills kept
        out[15000 + i] = (float)slab[p];
    }
}

// Per-class greedy NMS; writes kept scores directly into out.
__global__ void nms_kernel(float* __restrict__ out) {
    int c = blockIdx.x;
    __shared__ int s_n;
    __shared__ int s_wsum[4];
    __shared__ int s_pos[1024];
    __shared__ float4 s_box[1024];
    __shared__ float s_area[1024];
    __shared__ float s_scr[1024];
    __shared__ unsigned char s_supp[1024];
    if (threadIdx.x == 0) s_n = 0;
    __syncthreads();
    int lane = threadIdx.x & 31;
    int w = threadIdx.x >> 5;
    float offv = (float)c * 100000.0f;
    for (int base = 0; base < N_ALL; base += 128) {
        int i = base + threadIdx.x;
        bool pred = (i < N_ALL) && (g_slabel[i] == c) && (g_sscore[i] > CONF_T);
        unsigned int bal = __ballot_sync(0xFFFFFFFFu, pred);
        if (lane == 0) s_wsum[w] = __popc(bal);
        __syncthreads();
        int off = s_n;
        for (int ww = 0; ww < w; ww++) off += s_wsum[ww];
        int rank = off + __popc(bal & ((1u << lane) - 1u));
        if (pred && rank < 1024) {
            s_pos[rank] = i;
            float4 b = g_sbox[i];
            b.x += offv; b.y += offv; b.z += offv; b.w += offv;  // replicate ref quantization
            s_box[rank] = b;
            s_area[rank] = (b.z - b.x) * (b.w - b.y);
            s_scr[rank] = g_sscore[i];
            s_supp[rank] = 0;
        }
        __syncthreads();
        if (threadIdx.x == 0) s_n += s_wsum[0] + s_wsum[1] + s_wsum[2] + s_wsum[3];
        __syncthreads();
    }
    int n = (s_n < 1024) ? s_n : 1024;
    for (int a = 0; a < n; a++) {
        if (!s_supp[a]) {
            if (threadIdx.x == 0) out[12000 + s_pos[a]] = s_scr[a];
            float4 A = s_box[a];
            float arA = s_area[a];
            for (int b = a + 1 + (int)threadIdx.x; b < n; b += 128) {
                if (s_supp[b]) continue;
                float4 B = s_box[b];
                float ltx = fmaxf(A.x, B.x), lty = fmaxf(A.y, B.y);
                float rbx = fminf(A.z, B.z), rby = fminf(A.w, B.w);
                float wx = fmaxf(rbx - ltx, 0.0f), wy = fmaxf(rby - lty, 0.0f);
                float inter = wx * wy;
                float iou = inter / (arA + s_area[b] - inter + 1e-12f);
                if (iou > NMS_THR) s_supp[b] = 1;
            }
        }
        __syncthreads();
    }
}

// ---------------- launcher ----------------
extern "C" void kernel_launch(void* const* d_in, const int* in_sizes, int n_in,
                              void* d_out, int out_size) {
    (void)in_sizes; (void)n_in; (void)out_size;
    const float* obj0 = (const float*)d_in[0];
    const float* cls0 = (const float*)d_in[1];
    const float* reg0 = (const float*)d_in[2];
    const float* obj1 = (const float*)d_in[3];
    const float* cls1 = (const float*)d_in[4];
    const float* reg1 = (const float*)d_in[5];
    const float* obj2 = (const float*)d_in[6];
    const float* cls2 = (const float*)d_in[7];
    const float* reg2 = (const float*)d_in[8];
    const float* anc  = (const float*)d_in[9];
    float* out = (float*)d_out;

    cudaFuncSetAttribute(sort_topk_all,
                         cudaFuncAttributeMaxDynamicSharedMemorySize, SH_CAP * 8);

    zero_kernel<<<48, 1024>>>();
    rowmax_all<<<(RTOT * 4) / 256, 256>>>(obj0, cls0, obj1, cls1, obj2, cls2);
    findT_all<<<3, 256>>>();
    compact_all<<<(RTOT * 4) / 256, 256>>>(obj0, cls0, obj1, cls1, obj2, cls2);
    sort_topk_all<<<3, 1024, SH_CAP * 8>>>();
    fuse_kernel<<<1, 1024>>>(reg0, reg1, reg2, anc, out);
    nms_kernel<<<80, 128>>>(out);
}